// round 8
// baseline (speedup 1.0000x reference)
#include <cuda_runtime.h>
#include <cstdint>

#define N_NODES 100000
#define N_EDGES 1600000
#define DIM 64
#define HID 128
#define TILE_M 128
#define NT 782
#define TILES_PER_CTA 3
#define MLP_GRID 261

#if defined(__CUDA_ARCH_FEAT_SM103_ALL) || defined(__CUDA_ARCH_FEAT_SM100_ALL) || \
    defined(__CUDA_ARCH_FEAT_SM101_ALL)
#define HAS_TCGEN05 1
#else
#define HAS_TCGEN05 0
#endif

__device__ int g_idx_is64;
__device__ uint32_t g_w1t[DIM * HID];
__device__ uint32_t g_w2t[HID * DIM];
__device__ int g_off[N_NODES];     // counts -> exclusive prefix -> (after fill) inclusive end
__device__ int g_csr[N_EDGES];     // src ids grouped by dst

// ---------------------------------------------------------------------------
// helpers
// ---------------------------------------------------------------------------
__device__ __forceinline__ uint32_t smem_u32(const void* p) {
    uint32_t a;
    asm("{ .reg .u64 t; cvta.to.shared.u64 t, %1; cvt.u32.u64 %0, t; }" : "=r"(a) : "l"(p));
    return a;
}
__device__ __forceinline__ uint32_t elect_one() {
    uint32_t p;
    asm volatile("{ .reg .pred p; elect.sync _|p, 0xFFFFFFFF; selp.b32 %0, 1, 0, p; }" : "=r"(p));
    return p;
}
__device__ __forceinline__ uint32_t sw128(uint32_t b) { return b ^ ((b >> 3) & 0x70); }
__device__ __forceinline__ uint32_t cvt_tf32(float f) {
    uint32_t r;
    asm("cvt.rna.tf32.f32 %0, %1;" : "=r"(r) : "f"(f));
    return r;
}
__device__ __forceinline__ uint64_t make_desc(uint32_t addr) {
    return (uint64_t(2) << 61) | (uint64_t(1) << 46) | (uint64_t(64) << 32) |
           (uint64_t(1) << 16) | ((uint64_t)(addr >> 4) & 0x3FFF);
}
__device__ __forceinline__ unsigned int edge_dst(const void* ei_raw, int e) {
    if (g_idx_is64) return (unsigned int)((const long long*)ei_raw)[N_EDGES + e];
    return (unsigned int)((const int*)ei_raw)[N_EDGES + e];
}
__device__ __forceinline__ unsigned int edge_src(const void* ei_raw, int e) {
    if (g_idx_is64) return (unsigned int)((const long long*)ei_raw)[e];
    return (unsigned int)((const int*)ei_raw)[e];
}

#define MBAR_INIT(a, c) asm volatile("mbarrier.init.shared.b64 [%0], %1;" :: "r"(a), "r"(c) : "memory")
#define MBAR_INVAL(a)   asm volatile("mbarrier.inval.shared.b64 [%0];" :: "r"(a) : "memory")
#define MBAR_WAIT(a, ph) do {                                                     \
    uint32_t _m = (a), _p = (ph), _d;                                             \
    asm volatile("{ .reg .pred p; mbarrier.try_wait.parity.acquire.cta.shared::cta.b64 p, [%1], %2; selp.b32 %0,1,0,p; }" \
                 : "=r"(_d) : "r"(_m), "r"(_p) : "memory");                       \
    if (!_d) {                                                                    \
        asm volatile("{ .reg .pred P1; WL%=: mbarrier.try_wait.parity.acquire.cta.shared::cta.b64 P1, [%0], %1, 0x989680;" \
                     " @P1 bra.uni WD%=; bra.uni WL%=; WD%=: }"                   \
                     :: "r"(_m), "r"(_p) : "memory");                             \
    } } while (0)

#if HAS_TCGEN05
#define TC_ALLOC(sa, n)   asm volatile("tcgen05.alloc.cta_group::1.sync.aligned.shared::cta.b32 [%0], %1;" :: "r"(sa), "r"(n) : "memory")
#define TC_DEALLOC(t, n)  asm volatile("tcgen05.dealloc.cta_group::1.sync.aligned.b32 %0, %1;" :: "r"(t), "r"(n))
#define TC_RELINQ()       asm volatile("tcgen05.relinquish_alloc_permit.cta_group::1.sync.aligned;")
#define TC_COMMIT(mb)     asm volatile("tcgen05.commit.cta_group::1.mbarrier::arrive::one.shared::cluster.b64 [%0];" :: "r"(mb) : "memory")
#define TC_WAIT_LD()      asm volatile("tcgen05.wait::ld.sync.aligned;" ::: "memory")
#define TC_WAIT_ST()      asm volatile("tcgen05.wait::st.sync.aligned;" ::: "memory")
#define TC_FENCE_BEFORE() asm volatile("tcgen05.fence::before_thread_sync;" ::: "memory")
#define TC_FENCE_AFTER()  asm volatile("tcgen05.fence::after_thread_sync;" ::: "memory")
#define FENCE_ASYNC()     asm volatile("fence.proxy.async.shared::cta;" ::: "memory")

#define LDTM_X32(r, a)                                                              \
    asm volatile("tcgen05.ld.sync.aligned.32x32b.x32.b32 "                          \
        "{%0,%1,%2,%3,%4,%5,%6,%7,%8,%9,%10,%11,%12,%13,%14,%15,"                   \
        "%16,%17,%18,%19,%20,%21,%22,%23,%24,%25,%26,%27,%28,%29,%30,%31}, [%32];"  \
        : "=r"((r)[0]),"=r"((r)[1]),"=r"((r)[2]),"=r"((r)[3]),"=r"((r)[4]),"=r"((r)[5]),"=r"((r)[6]),"=r"((r)[7]), \
          "=r"((r)[8]),"=r"((r)[9]),"=r"((r)[10]),"=r"((r)[11]),"=r"((r)[12]),"=r"((r)[13]),"=r"((r)[14]),"=r"((r)[15]), \
          "=r"((r)[16]),"=r"((r)[17]),"=r"((r)[18]),"=r"((r)[19]),"=r"((r)[20]),"=r"((r)[21]),"=r"((r)[22]),"=r"((r)[23]), \
          "=r"((r)[24]),"=r"((r)[25]),"=r"((r)[26]),"=r"((r)[27]),"=r"((r)[28]),"=r"((r)[29]),"=r"((r)[30]),"=r"((r)[31]) \
        : "r"(a))

#define STTM_X32(a, r)                                                              \
    asm volatile("tcgen05.st.sync.aligned.32x32b.x32.b32 [%0], "                    \
        "{%1,%2,%3,%4,%5,%6,%7,%8,%9,%10,%11,%12,%13,%14,%15,%16,"                  \
        "%17,%18,%19,%20,%21,%22,%23,%24,%25,%26,%27,%28,%29,%30,%31,%32};"         \
        :: "r"(a),                                                                  \
           "r"((r)[0]),"r"((r)[1]),"r"((r)[2]),"r"((r)[3]),"r"((r)[4]),"r"((r)[5]),"r"((r)[6]),"r"((r)[7]), \
           "r"((r)[8]),"r"((r)[9]),"r"((r)[10]),"r"((r)[11]),"r"((r)[12]),"r"((r)[13]),"r"((r)[14]),"r"((r)[15]), \
           "r"((r)[16]),"r"((r)[17]),"r"((r)[18]),"r"((r)[19]),"r"((r)[20]),"r"((r)[21]),"r"((r)[22]),"r"((r)[23]), \
           "r"((r)[24]),"r"((r)[25]),"r"((r)[26]),"r"((r)[27]),"r"((r)[28]),"r"((r)[29]),"r"((r)[30]),"r"((r)[31]) \
        : "memory")

__device__ __forceinline__ void mma_tf32_ss(uint32_t d, uint64_t a, uint64_t b,
                                            uint32_t idesc, bool acc) {
    uint32_t e = acc ? 1u : 0u;
    asm volatile("{ .reg .pred p; setp.ne.u32 p, %4, 0;"
                 " tcgen05.mma.cta_group::1.kind::tf32 [%0], %1, %2, %3, p; }"
                 :: "r"(d), "l"(a), "l"(b), "r"(idesc), "r"(e) : "memory");
}
__device__ __forceinline__ void mma_tf32_ts(uint32_t d, uint32_t a, uint64_t b,
                                            uint32_t idesc, bool acc) {
    uint32_t e = acc ? 1u : 0u;
    asm volatile("{ .reg .pred p; setp.ne.u32 p, %4, 0;"
                 " tcgen05.mma.cta_group::1.kind::tf32 [%0], [%1], %2, %3, p; }"
                 :: "r"(d), "r"(a), "l"(b), "r"(idesc), "r"(e) : "memory");
}
#endif

// ---------------------------------------------------------------------------
// Kernel 0: detect int32 vs int64 edge index
// ---------------------------------------------------------------------------
__global__ void detect_kernel(const int* __restrict__ ei32) {
    int any = 0;
    #pragma unroll
    for (int i = 0; i < 64; i++) any |= ei32[2 * i + 1];
    g_idx_is64 = (any == 0) ? 1 : 0;
}

// ---------------------------------------------------------------------------
// Kernel 0b: precompute swizzled tf32 weight images
// ---------------------------------------------------------------------------
__global__ void prep_w_kernel(const float* __restrict__ W1,
                              const float* __restrict__ W2) {
    int idx = blockIdx.x * blockDim.x + threadIdx.x;
    if (idx >= DIM * HID) return;
    {
        int j = idx & 127, k = idx >> 7;
        uint32_t byte = ((j >> 3) + (k >> 5) * 16) * 1024 + (j & 7) * 128 + (k & 31) * 4;
        g_w1t[sw128(byte) >> 2] = cvt_tf32(W1[k * HID + j]);
    }
    {
        int d = idx & 63, k = idx >> 6;
        uint32_t byte = ((d >> 3) + (k >> 5) * 8) * 1024 + (d & 7) * 128 + (k & 31) * 4;
        g_w2t[sw128(byte) >> 2] = cvt_tf32(W2[k * DIM + d]);
    }
}

// ---------------------------------------------------------------------------
// CSR build: zero counts -> count -> scan -> fill
// ---------------------------------------------------------------------------
__global__ void zero_cnt_kernel() {
    int i = blockIdx.x * blockDim.x + threadIdx.x;
    if (i < N_NODES) g_off[i] = 0;
}

__global__ void count_kernel(const void* __restrict__ ei_raw) {
    int e = blockIdx.x * blockDim.x + threadIdx.x;
    if (e >= N_EDGES) return;
    unsigned int d = edge_dst(ei_raw, e);
    if (d < N_NODES) atomicAdd(&g_off[d], 1);
}

// single-block exclusive scan over g_off (100k ints), in place
__global__ __launch_bounds__(1024, 1) void scan_kernel() {
    __shared__ int ts[1024];
    const int CH = (N_NODES + 1023) / 1024;   // 98
    int t = threadIdx.x;
    int lo = t * CH, hi = min(lo + CH, N_NODES);

    int sum = 0;
    for (int i = lo; i < hi; i++) sum += g_off[i];
    ts[t] = sum;
    __syncthreads();
    #pragma unroll
    for (int off = 1; off < 1024; off <<= 1) {
        int v = (t >= off) ? ts[t - off] : 0;
        __syncthreads();
        ts[t] += v;
        __syncthreads();
    }
    int run = ts[t] - sum;   // exclusive prefix of this chunk
    for (int i = lo; i < hi; i++) {
        int v = g_off[i];
        g_off[i] = run;
        run += v;
    }
}

__global__ void fill_kernel(const void* __restrict__ ei_raw) {
    int e = blockIdx.x * blockDim.x + threadIdx.x;
    if (e >= N_EDGES) return;
    unsigned int d = edge_dst(ei_raw, e);
    unsigned int s = edge_src(ei_raw, e);
    if (d >= N_NODES || s >= N_NODES) return;
    int slot = atomicAdd(&g_off[d], 1);       // destructive: g_off[d] becomes end(d)
    g_csr[slot] = (int)s;
}

// ---------------------------------------------------------------------------
// Gather-aggregate v2: warp per node, lane = float2 slice (32 lanes = 256B row).
// Neighbor indices staged in smem per warp, consumed in groups of 8 fully
// independent LDG.64 into 4 accumulators -> MLP ~8, L2 latency hidden.
// ---------------------------------------------------------------------------
__global__ __launch_bounds__(256) void gather_kernel(const float* __restrict__ x,
                                                     float* __restrict__ out) {
    __shared__ int stage[8][132];
    int wl = threadIdx.x >> 5;                 // warp within block
    int w  = (blockIdx.x * blockDim.x + threadIdx.x) >> 5;   // node
    if (w >= N_NODES) return;
    int lane = threadIdx.x & 31;

    int end   = g_off[w];
    int start = (w == 0) ? 0 : g_off[w - 1];

    const float2* xp = (const float2*)x;
    float2 a0 = __ldg(xp + (size_t)w * 32 + lane);   // self term
    float2 a1 = make_float2(0.f, 0.f);
    float2 a2 = make_float2(0.f, 0.f);
    float2 a3 = make_float2(0.f, 0.f);

    for (int b = start; b < end; b += 128) {
        int m = min(128, end - b);
        for (int i = lane; i < m; i += 32) stage[wl][i] = __ldg(&g_csr[b + i]);
        __syncwarp();

        int i = 0;
        for (; i + 8 <= m; i += 8) {
            int n0 = stage[wl][i + 0], n1 = stage[wl][i + 1];
            int n2 = stage[wl][i + 2], n3 = stage[wl][i + 3];
            int n4 = stage[wl][i + 4], n5 = stage[wl][i + 5];
            int n6 = stage[wl][i + 6], n7 = stage[wl][i + 7];
            float2 v0 = __ldg(xp + (size_t)n0 * 32 + lane);
            float2 v1 = __ldg(xp + (size_t)n1 * 32 + lane);
            float2 v2 = __ldg(xp + (size_t)n2 * 32 + lane);
            float2 v3 = __ldg(xp + (size_t)n3 * 32 + lane);
            float2 v4 = __ldg(xp + (size_t)n4 * 32 + lane);
            float2 v5 = __ldg(xp + (size_t)n5 * 32 + lane);
            float2 v6 = __ldg(xp + (size_t)n6 * 32 + lane);
            float2 v7 = __ldg(xp + (size_t)n7 * 32 + lane);
            a0.x += v0.x; a0.y += v0.y;  a1.x += v1.x; a1.y += v1.y;
            a2.x += v2.x; a2.y += v2.y;  a3.x += v3.x; a3.y += v3.y;
            a0.x += v4.x; a0.y += v4.y;  a1.x += v5.x; a1.y += v5.y;
            a2.x += v6.x; a2.y += v6.y;  a3.x += v7.x; a3.y += v7.y;
        }
        for (; i < m; i++) {
            int nb = stage[wl][i];
            float2 v = __ldg(xp + (size_t)nb * 32 + lane);
            a0.x += v.x; a0.y += v.y;
        }
        __syncwarp();
    }

    a0.x += a1.x + a2.x + a3.x;
    a0.y += a1.y + a2.y + a3.y;
    *((float2*)(out + (size_t)w * DIM) + lane) = a0;
}

// ---------------------------------------------------------------------------
// MLP via tcgen05 (buf already holds self+neighbors)
// ---------------------------------------------------------------------------
#define SM_TMEM  0
#define SM_MBAR  8
#define SM_X     1024
#define SM_W1    (SM_X + 32768)
#define SM_W2    (SM_W1 + 32768)
#define SM_B1    (SM_W2 + 32768)
#define SM_B2    (SM_B1 + 512)
#define SM_TOTAL (SM_B2 + 512)

#define T_D1   0
#define T_A2   128
#define T_D2   0
#define T_COLS 256

#define IDESC1 ((1u << 4) | (2u << 7) | (2u << 10) | ((HID / 8) << 17) | ((TILE_M / 16) << 24))
#define IDESC2 ((1u << 4) | (2u << 7) | (2u << 10) | ((DIM / 8) << 17) | ((TILE_M / 16) << 24))

__global__ __launch_bounds__(256, 2)
void mlp_tc_kernel(float* __restrict__ buf,
                   const float* __restrict__ b1, const float* __restrict__ b2) {
#if HAS_TCGEN05
    extern __shared__ char smem[];
    uint32_t sb = smem_u32(smem);
    int tid = threadIdx.x;
    int wid = tid >> 5;
    int lid = tid & 31;
    int wg  = wid >> 2;
    uint32_t woff = (uint32_t)(wid & 3) << 21;

    if (wid == 0) {
        TC_ALLOC(sb + SM_TMEM, T_COLS);
        TC_RELINQ();
        if (elect_one()) MBAR_INIT(sb + SM_MBAR, 1);
    }
    __syncthreads();
    uint32_t tmem;
    asm volatile("ld.shared.b32 %0, [%1];" : "=r"(tmem) : "r"(sb + SM_TMEM));

    {
        const uint4* s1 = (const uint4*)g_w1t;
        const uint4* s2 = (const uint4*)g_w2t;
        uint4* d1 = (uint4*)(smem + SM_W1);
        uint4* d2 = (uint4*)(smem + SM_W2);
        for (int i = tid; i < DIM * HID / 4; i += 256) {
            d1[i] = __ldg(s1 + i);
            d2[i] = __ldg(s2 + i);
        }
    }
    if (tid < HID) ((float*)(smem + SM_B1))[tid] = b1[tid];
    if (tid < DIM) ((float*)(smem + SM_B2))[tid] = b2[tid];

    int ph = 0;
    #pragma unroll 1
    for (int t = 0; t < TILES_PER_CTA; t++) {
        int tile = blockIdx.x * TILES_PER_CTA + t;
        if (tile >= NT) break;
        int base = tile * TILE_M;

        __syncthreads();

        for (int i = tid; i < TILE_M * (DIM / 4); i += 256) {
            int row = i >> 4;
            int c4  = i & 15;
            int node = base + row;
            float4 s = make_float4(0.f, 0.f, 0.f, 0.f);
            if (node < N_NODES)
                s = __ldg(((const float4*)(buf + (size_t)node * DIM)) + c4);
            uint32_t byte = ((row >> 3) + (c4 >> 3) * 16) * 1024 + (row & 7) * 128 + (c4 & 7) * 16;
            *(uint4*)(smem + SM_X + sw128(byte)) =
                make_uint4(cvt_tf32(s.x), cvt_tf32(s.y), cvt_tf32(s.z), cvt_tf32(s.w));
        }
        FENCE_ASYNC();
        __syncthreads();

        if (wid == 0) {
            TC_FENCE_AFTER();
            if (elect_one()) {
                uint64_t ad = make_desc(sb + SM_X);
                uint64_t bd = make_desc(sb + SM_W1);
                #pragma unroll
                for (int s = 0; s < 8; s++) {
                    uint64_t off = (uint64_t)((s >> 2) * 1024 + (s & 3) * 2);
                    mma_tf32_ss(tmem + T_D1, ad + off, bd + off, IDESC1, s > 0);
                }
                TC_COMMIT(sb + SM_MBAR);
            }
        }
        MBAR_WAIT(sb + SM_MBAR, ph); ph ^= 1;
        TC_FENCE_AFTER();

        {
            const float* b1s = (const float*)(smem + SM_B1);
            #pragma unroll
            for (int blk = 0; blk < 2; blk++) {
                int c0 = wg * 64 + blk * 32;
                uint32_t r[32];
                LDTM_X32(r, tmem + woff + T_D1 + c0);
                TC_WAIT_LD();
                #pragma unroll
                for (int i = 0; i < 32; i++) {
                    float f = __uint_as_float(r[i]) + b1s[c0 + i];
                    r[i] = cvt_tf32(fmaxf(f, 0.f));
                }
                STTM_X32(tmem + woff + T_A2 + c0, r);
            }
            TC_WAIT_ST();
        }
        TC_FENCE_BEFORE();
        __syncthreads();

        if (wid == 0) {
            TC_FENCE_AFTER();
            if (elect_one()) {
                uint64_t bd = make_desc(sb + SM_W2);
                #pragma unroll
                for (int s = 0; s < 16; s++) {
                    uint64_t off = (uint64_t)((s >> 2) * 512 + (s & 3) * 2);
                    mma_tf32_ts(tmem + T_D2, tmem + T_A2 + s * 8, bd + off, IDESC2, s > 0);
                }
                TC_COMMIT(sb + SM_MBAR);
            }
        }
        MBAR_WAIT(sb + SM_MBAR, ph); ph ^= 1;
        TC_FENCE_AFTER();

        {
            const float* b2s = (const float*)(smem + SM_B2);
            int node = base + (wid & 3) * 32 + lid;
            int c0 = wg * 32;
            uint32_t r[32];
            LDTM_X32(r, tmem + woff + T_D2 + c0);
            TC_WAIT_LD();
            if (node < N_NODES) {
                float* op = buf + (size_t)node * DIM + c0;
                #pragma unroll
                for (int g = 0; g < 8; g++) {
                    float4 v;
                    v.x = __uint_as_float(r[4 * g + 0]) + b2s[c0 + 4 * g + 0];
                    v.y = __uint_as_float(r[4 * g + 1]) + b2s[c0 + 4 * g + 1];
                    v.z = __uint_as_float(r[4 * g + 2]) + b2s[c0 + 4 * g + 2];
                    v.w = __uint_as_float(r[4 * g + 3]) + b2s[c0 + 4 * g + 3];
                    *(float4*)(op + 4 * g) = v;
                }
            }
        }
        TC_FENCE_BEFORE();
    }

    __syncthreads();
    if (wid == 0) {
        if (elect_one()) MBAR_INVAL(sb + SM_MBAR);
        TC_DEALLOC(tmem, T_COLS);
    }
#endif
}

// ---------------------------------------------------------------------------
// Launch
// ---------------------------------------------------------------------------
extern "C" void kernel_launch(void* const* d_in, const int* in_sizes, int n_in,
                              void* d_out, int out_size) {
    const float* x  = (const float*)d_in[0];
    const void*  ei = d_in[1];
    const float* W1 = (const float*)d_in[2];
    const float* b1 = (const float*)d_in[3];
    const float* W2 = (const float*)d_in[4];
    const float* b2 = (const float*)d_in[5];
    float* out = (float*)d_out;

    cudaFuncSetAttribute(mlp_tc_kernel, cudaFuncAttributeMaxDynamicSharedMemorySize,
                         SM_TOTAL);

    detect_kernel<<<1, 1>>>((const int*)ei);
    prep_w_kernel<<<(DIM * HID + 255) / 256, 256>>>(W1, W2);

    // CSR build
    zero_cnt_kernel<<<(N_NODES + 255) / 256, 256>>>();
    count_kernel<<<(N_EDGES + 255) / 256, 256>>>(ei);
    scan_kernel<<<1, 1024>>>();
    fill_kernel<<<(N_EDGES + 255) / 256, 256>>>(ei);

    // aggregate (self + neighbors), no float atomics
    gather_kernel<<<(N_NODES * 32 + 255) / 256, 256>>>(x, out);

    // MLP in place
    mlp_tc_kernel<<<MLP_GRID, 256, SM_TOTAL>>>(out, b1, b2);
}

// round 9
// speedup vs baseline: 1.8622x; 1.8622x over previous
#include <cuda_runtime.h>
#include <cstdint>

#define N_NODES 100000
#define N_EDGES 1600000
#define DIM 64
#define HID 128
#define TILE_M 128
#define NT 782
#define TILES_PER_CTA 3
#define MLP_GRID 261
#define SCAN_BLOCKS 98   // ceil(100000/1024)

#if defined(__CUDA_ARCH_FEAT_SM103_ALL) || defined(__CUDA_ARCH_FEAT_SM100_ALL) || \
    defined(__CUDA_ARCH_FEAT_SM101_ALL)
#define HAS_TCGEN05 1
#else
#define HAS_TCGEN05 0
#endif

__device__ int g_idx_is64;
__device__ uint32_t g_w1t[DIM * HID];
__device__ uint32_t g_w2t[HID * DIM];
__device__ int g_off[N_NODES];     // counts -> exclusive prefix -> (after fill) inclusive end
__device__ int g_csr[N_EDGES];     // src ids grouped by dst
__device__ int g_blk[128];         // block sums for the scan

// ---------------------------------------------------------------------------
// helpers
// ---------------------------------------------------------------------------
__device__ __forceinline__ uint32_t smem_u32(const void* p) {
    uint32_t a;
    asm("{ .reg .u64 t; cvta.to.shared.u64 t, %1; cvt.u32.u64 %0, t; }" : "=r"(a) : "l"(p));
    return a;
}
__device__ __forceinline__ uint32_t elect_one() {
    uint32_t p;
    asm volatile("{ .reg .pred p; elect.sync _|p, 0xFFFFFFFF; selp.b32 %0, 1, 0, p; }" : "=r"(p));
    return p;
}
__device__ __forceinline__ uint32_t sw128(uint32_t b) { return b ^ ((b >> 3) & 0x70); }
__device__ __forceinline__ uint32_t cvt_tf32(float f) {
    uint32_t r;
    asm("cvt.rna.tf32.f32 %0, %1;" : "=r"(r) : "f"(f));
    return r;
}
__device__ __forceinline__ uint64_t make_desc(uint32_t addr) {
    return (uint64_t(2) << 61) | (uint64_t(1) << 46) | (uint64_t(64) << 32) |
           (uint64_t(1) << 16) | ((uint64_t)(addr >> 4) & 0x3FFF);
}
__device__ __forceinline__ unsigned int edge_dst(const void* ei_raw, int e) {
    if (g_idx_is64) return (unsigned int)((const long long*)ei_raw)[N_EDGES + e];
    return (unsigned int)((const int*)ei_raw)[N_EDGES + e];
}
__device__ __forceinline__ unsigned int edge_src(const void* ei_raw, int e) {
    if (g_idx_is64) return (unsigned int)((const long long*)ei_raw)[e];
    return (unsigned int)((const int*)ei_raw)[e];
}

#define MBAR_INIT(a, c) asm volatile("mbarrier.init.shared.b64 [%0], %1;" :: "r"(a), "r"(c) : "memory")
#define MBAR_INVAL(a)   asm volatile("mbarrier.inval.shared.b64 [%0];" :: "r"(a) : "memory")
#define MBAR_WAIT(a, ph) do {                                                     \
    uint32_t _m = (a), _p = (ph), _d;                                             \
    asm volatile("{ .reg .pred p; mbarrier.try_wait.parity.acquire.cta.shared::cta.b64 p, [%1], %2; selp.b32 %0,1,0,p; }" \
                 : "=r"(_d) : "r"(_m), "r"(_p) : "memory");                       \
    if (!_d) {                                                                    \
        asm volatile("{ .reg .pred P1; WL%=: mbarrier.try_wait.parity.acquire.cta.shared::cta.b64 P1, [%0], %1, 0x989680;" \
                     " @P1 bra.uni WD%=; bra.uni WL%=; WD%=: }"                   \
                     :: "r"(_m), "r"(_p) : "memory");                             \
    } } while (0)

#if HAS_TCGEN05
#define TC_ALLOC(sa, n)   asm volatile("tcgen05.alloc.cta_group::1.sync.aligned.shared::cta.b32 [%0], %1;" :: "r"(sa), "r"(n) : "memory")
#define TC_DEALLOC(t, n)  asm volatile("tcgen05.dealloc.cta_group::1.sync.aligned.b32 %0, %1;" :: "r"(t), "r"(n))
#define TC_RELINQ()       asm volatile("tcgen05.relinquish_alloc_permit.cta_group::1.sync.aligned;")
#define TC_COMMIT(mb)     asm volatile("tcgen05.commit.cta_group::1.mbarrier::arrive::one.shared::cluster.b64 [%0];" :: "r"(mb) : "memory")
#define TC_WAIT_LD()      asm volatile("tcgen05.wait::ld.sync.aligned;" ::: "memory")
#define TC_WAIT_ST()      asm volatile("tcgen05.wait::st.sync.aligned;" ::: "memory")
#define TC_FENCE_BEFORE() asm volatile("tcgen05.fence::before_thread_sync;" ::: "memory")
#define TC_FENCE_AFTER()  asm volatile("tcgen05.fence::after_thread_sync;" ::: "memory")
#define FENCE_ASYNC()     asm volatile("fence.proxy.async.shared::cta;" ::: "memory")

#define LDTM_X32(r, a)                                                              \
    asm volatile("tcgen05.ld.sync.aligned.32x32b.x32.b32 "                          \
        "{%0,%1,%2,%3,%4,%5,%6,%7,%8,%9,%10,%11,%12,%13,%14,%15,"                   \
        "%16,%17,%18,%19,%20,%21,%22,%23,%24,%25,%26,%27,%28,%29,%30,%31}, [%32];"  \
        : "=r"((r)[0]),"=r"((r)[1]),"=r"((r)[2]),"=r"((r)[3]),"=r"((r)[4]),"=r"((r)[5]),"=r"((r)[6]),"=r"((r)[7]), \
          "=r"((r)[8]),"=r"((r)[9]),"=r"((r)[10]),"=r"((r)[11]),"=r"((r)[12]),"=r"((r)[13]),"=r"((r)[14]),"=r"((r)[15]), \
          "=r"((r)[16]),"=r"((r)[17]),"=r"((r)[18]),"=r"((r)[19]),"=r"((r)[20]),"=r"((r)[21]),"=r"((r)[22]),"=r"((r)[23]), \
          "=r"((r)[24]),"=r"((r)[25]),"=r"((r)[26]),"=r"((r)[27]),"=r"((r)[28]),"=r"((r)[29]),"=r"((r)[30]),"=r"((r)[31]) \
        : "r"(a))

#define STTM_X32(a, r)                                                              \
    asm volatile("tcgen05.st.sync.aligned.32x32b.x32.b32 [%0], "                    \
        "{%1,%2,%3,%4,%5,%6,%7,%8,%9,%10,%11,%12,%13,%14,%15,%16,"                  \
        "%17,%18,%19,%20,%21,%22,%23,%24,%25,%26,%27,%28,%29,%30,%31,%32};"         \
        :: "r"(a),                                                                  \
           "r"((r)[0]),"r"((r)[1]),"r"((r)[2]),"r"((r)[3]),"r"((r)[4]),"r"((r)[5]),"r"((r)[6]),"r"((r)[7]), \
           "r"((r)[8]),"r"((r)[9]),"r"((r)[10]),"r"((r)[11]),"r"((r)[12]),"r"((r)[13]),"r"((r)[14]),"r"((r)[15]), \
           "r"((r)[16]),"r"((r)[17]),"r"((r)[18]),"r"((r)[19]),"r"((r)[20]),"r"((r)[21]),"r"((r)[22]),"r"((r)[23]), \
           "r"((r)[24]),"r"((r)[25]),"r"((r)[26]),"r"((r)[27]),"r"((r)[28]),"r"((r)[29]),"r"((r)[30]),"r"((r)[31]) \
        : "memory")

__device__ __forceinline__ void mma_tf32_ss(uint32_t d, uint64_t a, uint64_t b,
                                            uint32_t idesc, bool acc) {
    uint32_t e = acc ? 1u : 0u;
    asm volatile("{ .reg .pred p; setp.ne.u32 p, %4, 0;"
                 " tcgen05.mma.cta_group::1.kind::tf32 [%0], %1, %2, %3, p; }"
                 :: "r"(d), "l"(a), "l"(b), "r"(idesc), "r"(e) : "memory");
}
__device__ __forceinline__ void mma_tf32_ts(uint32_t d, uint32_t a, uint64_t b,
                                            uint32_t idesc, bool acc) {
    uint32_t e = acc ? 1u : 0u;
    asm volatile("{ .reg .pred p; setp.ne.u32 p, %4, 0;"
                 " tcgen05.mma.cta_group::1.kind::tf32 [%0], [%1], %2, %3, p; }"
                 :: "r"(d), "r"(a), "l"(b), "r"(idesc), "r"(e) : "memory");
}
#endif

// ---------------------------------------------------------------------------
// Kernel 0: detect int32 vs int64 edge index
// ---------------------------------------------------------------------------
__global__ void detect_kernel(const int* __restrict__ ei32) {
    int any = 0;
    #pragma unroll
    for (int i = 0; i < 64; i++) any |= ei32[2 * i + 1];
    g_idx_is64 = (any == 0) ? 1 : 0;
}

// ---------------------------------------------------------------------------
// Kernel 0b: precompute swizzled tf32 weight images
// ---------------------------------------------------------------------------
__global__ void prep_w_kernel(const float* __restrict__ W1,
                              const float* __restrict__ W2) {
    int idx = blockIdx.x * blockDim.x + threadIdx.x;
    if (idx >= DIM * HID) return;
    {
        int j = idx & 127, k = idx >> 7;
        uint32_t byte = ((j >> 3) + (k >> 5) * 16) * 1024 + (j & 7) * 128 + (k & 31) * 4;
        g_w1t[sw128(byte) >> 2] = cvt_tf32(W1[k * HID + j]);
    }
    {
        int d = idx & 63, k = idx >> 6;
        uint32_t byte = ((d >> 3) + (k >> 5) * 8) * 1024 + (d & 7) * 128 + (k & 31) * 4;
        g_w2t[sw128(byte) >> 2] = cvt_tf32(W2[k * DIM + d]);
    }
}

// ---------------------------------------------------------------------------
// CSR build: zero -> count -> coalesced 3-phase scan -> fill
// ---------------------------------------------------------------------------
__global__ void zero_cnt_kernel() {
    int i = blockIdx.x * blockDim.x + threadIdx.x;
    if (i < N_NODES) g_off[i] = 0;
}

__global__ void count_kernel(const void* __restrict__ ei_raw) {
    int e = blockIdx.x * blockDim.x + threadIdx.x;
    if (e >= N_EDGES) return;
    unsigned int d = edge_dst(ei_raw, e);
    if (d < N_NODES) atomicAdd(&g_off[d], 1);
}

// scanA: per-1024-block sums (coalesced)
__global__ __launch_bounds__(1024) void scanA_kernel() {
    int i = blockIdx.x * 1024 + threadIdx.x;
    int v = (i < N_NODES) ? g_off[i] : 0;
    #pragma unroll
    for (int o = 16; o > 0; o >>= 1) v += __shfl_down_sync(0xffffffffu, v, o);
    __shared__ int ws[32];
    if ((threadIdx.x & 31) == 0) ws[threadIdx.x >> 5] = v;
    __syncthreads();
    if (threadIdx.x < 32) {
        int s = ws[threadIdx.x];
        #pragma unroll
        for (int o = 16; o > 0; o >>= 1) s += __shfl_down_sync(0xffffffffu, s, o);
        if (threadIdx.x == 0) g_blk[blockIdx.x] = s;
    }
}

// scanB: exclusive scan of the 98 block sums (single small block)
__global__ __launch_bounds__(128) void scanB_kernel() {
    __shared__ int ts[128];
    int t = threadIdx.x;
    int v = (t < SCAN_BLOCKS) ? g_blk[t] : 0;
    ts[t] = v;
    __syncthreads();
    #pragma unroll
    for (int o = 1; o < 128; o <<= 1) {
        int u = (t >= o) ? ts[t - o] : 0;
        __syncthreads();
        ts[t] += u;
        __syncthreads();
    }
    if (t < SCAN_BLOCKS) g_blk[t] = ts[t] - v;   // exclusive
}

// scanC: per-element exclusive prefix within block + block offset (coalesced)
__global__ __launch_bounds__(1024) void scanC_kernel() {
    int t = threadIdx.x;
    int lane = t & 31, w = t >> 5;
    int i = blockIdx.x * 1024 + t;
    int v = (i < N_NODES) ? g_off[i] : 0;

    // inclusive warp scan
    int s = v;
    #pragma unroll
    for (int o = 1; o < 32; o <<= 1) {
        int u = __shfl_up_sync(0xffffffffu, s, o);
        if (lane >= o) s += u;
    }
    __shared__ int ws[32];
    if (lane == 31) ws[w] = s;
    __syncthreads();
    if (w == 0) {
        int x2 = ws[lane];
        #pragma unroll
        for (int o = 1; o < 32; o <<= 1) {
            int u = __shfl_up_sync(0xffffffffu, x2, o);
            if (lane >= o) x2 += u;
        }
        ws[lane] = x2;
    }
    __syncthreads();
    int warp_excl = (w == 0) ? 0 : ws[w - 1];
    int excl = (s - v) + warp_excl + g_blk[blockIdx.x];
    if (i < N_NODES) g_off[i] = excl;
}

__global__ void fill_kernel(const void* __restrict__ ei_raw) {
    int e = blockIdx.x * blockDim.x + threadIdx.x;
    if (e >= N_EDGES) return;
    unsigned int d = edge_dst(ei_raw, e);
    unsigned int s = edge_src(ei_raw, e);
    if (d >= N_NODES || s >= N_NODES) return;
    int slot = atomicAdd(&g_off[d], 1);       // destructive: g_off[d] becomes end(d)
    g_csr[slot] = (int)s;
}

// ---------------------------------------------------------------------------
// Gather-aggregate: warp per node, lane = float2 slice; staged indices,
// groups of 8 independent LDG.64 into 4 accumulators.
// ---------------------------------------------------------------------------
__global__ __launch_bounds__(256) void gather_kernel(const float* __restrict__ x,
                                                     float* __restrict__ out) {
    __shared__ int stage[8][132];
    int wl = threadIdx.x >> 5;
    int w  = (blockIdx.x * blockDim.x + threadIdx.x) >> 5;
    if (w >= N_NODES) return;
    int lane = threadIdx.x & 31;

    int end   = g_off[w];
    int start = (w == 0) ? 0 : g_off[w - 1];

    const float2* xp = (const float2*)x;
    float2 a0 = __ldg(xp + (size_t)w * 32 + lane);   // self term
    float2 a1 = make_float2(0.f, 0.f);
    float2 a2 = make_float2(0.f, 0.f);
    float2 a3 = make_float2(0.f, 0.f);

    for (int b = start; b < end; b += 128) {
        int m = min(128, end - b);
        for (int i = lane; i < m; i += 32) stage[wl][i] = __ldg(&g_csr[b + i]);
        __syncwarp();

        int i = 0;
        for (; i + 8 <= m; i += 8) {
            int n0 = stage[wl][i + 0], n1 = stage[wl][i + 1];
            int n2 = stage[wl][i + 2], n3 = stage[wl][i + 3];
            int n4 = stage[wl][i + 4], n5 = stage[wl][i + 5];
            int n6 = stage[wl][i + 6], n7 = stage[wl][i + 7];
            float2 v0 = __ldg(xp + (size_t)n0 * 32 + lane);
            float2 v1 = __ldg(xp + (size_t)n1 * 32 + lane);
            float2 v2 = __ldg(xp + (size_t)n2 * 32 + lane);
            float2 v3 = __ldg(xp + (size_t)n3 * 32 + lane);
            float2 v4 = __ldg(xp + (size_t)n4 * 32 + lane);
            float2 v5 = __ldg(xp + (size_t)n5 * 32 + lane);
            float2 v6 = __ldg(xp + (size_t)n6 * 32 + lane);
            float2 v7 = __ldg(xp + (size_t)n7 * 32 + lane);
            a0.x += v0.x; a0.y += v0.y;  a1.x += v1.x; a1.y += v1.y;
            a2.x += v2.x; a2.y += v2.y;  a3.x += v3.x; a3.y += v3.y;
            a0.x += v4.x; a0.y += v4.y;  a1.x += v5.x; a1.y += v5.y;
            a2.x += v6.x; a2.y += v6.y;  a3.x += v7.x; a3.y += v7.y;
        }
        for (; i < m; i++) {
            int nb = stage[wl][i];
            float2 v = __ldg(xp + (size_t)nb * 32 + lane);
            a0.x += v.x; a0.y += v.y;
        }
        __syncwarp();
    }

    a0.x += a1.x + a2.x + a3.x;
    a0.y += a1.y + a2.y + a3.y;
    *((float2*)(out + (size_t)w * DIM) + lane) = a0;
}

// ---------------------------------------------------------------------------
// MLP via tcgen05 (buf already holds self+neighbors)
// ---------------------------------------------------------------------------
#define SM_TMEM  0
#define SM_MBAR  8
#define SM_X     1024
#define SM_W1    (SM_X + 32768)
#define SM_W2    (SM_W1 + 32768)
#define SM_B1    (SM_W2 + 32768)
#define SM_B2    (SM_B1 + 512)
#define SM_TOTAL (SM_B2 + 512)

#define T_D1   0
#define T_A2   128
#define T_D2   0
#define T_COLS 256

#define IDESC1 ((1u << 4) | (2u << 7) | (2u << 10) | ((HID / 8) << 17) | ((TILE_M / 16) << 24))
#define IDESC2 ((1u << 4) | (2u << 7) | (2u << 10) | ((DIM / 8) << 17) | ((TILE_M / 16) << 24))

__global__ __launch_bounds__(256, 2)
void mlp_tc_kernel(float* __restrict__ buf,
                   const float* __restrict__ b1, const float* __restrict__ b2) {
#if HAS_TCGEN05
    extern __shared__ char smem[];
    uint32_t sb = smem_u32(smem);
    int tid = threadIdx.x;
    int wid = tid >> 5;
    int lid = tid & 31;
    int wg  = wid >> 2;
    uint32_t woff = (uint32_t)(wid & 3) << 21;

    if (wid == 0) {
        TC_ALLOC(sb + SM_TMEM, T_COLS);
        TC_RELINQ();
        if (elect_one()) MBAR_INIT(sb + SM_MBAR, 1);
    }
    __syncthreads();
    uint32_t tmem;
    asm volatile("ld.shared.b32 %0, [%1];" : "=r"(tmem) : "r"(sb + SM_TMEM));

    {
        const uint4* s1 = (const uint4*)g_w1t;
        const uint4* s2 = (const uint4*)g_w2t;
        uint4* d1 = (uint4*)(smem + SM_W1);
        uint4* d2 = (uint4*)(smem + SM_W2);
        for (int i = tid; i < DIM * HID / 4; i += 256) {
            d1[i] = __ldg(s1 + i);
            d2[i] = __ldg(s2 + i);
        }
    }
    if (tid < HID) ((float*)(smem + SM_B1))[tid] = b1[tid];
    if (tid < DIM) ((float*)(smem + SM_B2))[tid] = b2[tid];

    int ph = 0;
    #pragma unroll 1
    for (int t = 0; t < TILES_PER_CTA; t++) {
        int tile = blockIdx.x * TILES_PER_CTA + t;
        if (tile >= NT) break;
        int base = tile * TILE_M;

        __syncthreads();

        for (int i = tid; i < TILE_M * (DIM / 4); i += 256) {
            int row = i >> 4;
            int c4  = i & 15;
            int node = base + row;
            float4 s = make_float4(0.f, 0.f, 0.f, 0.f);
            if (node < N_NODES)
                s = __ldg(((const float4*)(buf + (size_t)node * DIM)) + c4);
            uint32_t byte = ((row >> 3) + (c4 >> 3) * 16) * 1024 + (row & 7) * 128 + (c4 & 7) * 16;
            *(uint4*)(smem + SM_X + sw128(byte)) =
                make_uint4(cvt_tf32(s.x), cvt_tf32(s.y), cvt_tf32(s.z), cvt_tf32(s.w));
        }
        FENCE_ASYNC();
        __syncthreads();

        if (wid == 0) {
            TC_FENCE_AFTER();
            if (elect_one()) {
                uint64_t ad = make_desc(sb + SM_X);
                uint64_t bd = make_desc(sb + SM_W1);
                #pragma unroll
                for (int s = 0; s < 8; s++) {
                    uint64_t off = (uint64_t)((s >> 2) * 1024 + (s & 3) * 2);
                    mma_tf32_ss(tmem + T_D1, ad + off, bd + off, IDESC1, s > 0);
                }
                TC_COMMIT(sb + SM_MBAR);
            }
        }
        MBAR_WAIT(sb + SM_MBAR, ph); ph ^= 1;
        TC_FENCE_AFTER();

        {
            const float* b1s = (const float*)(smem + SM_B1);
            #pragma unroll
            for (int blk = 0; blk < 2; blk++) {
                int c0 = wg * 64 + blk * 32;
                uint32_t r[32];
                LDTM_X32(r, tmem + woff + T_D1 + c0);
                TC_WAIT_LD();
                #pragma unroll
                for (int i = 0; i < 32; i++) {
                    float f = __uint_as_float(r[i]) + b1s[c0 + i];
                    r[i] = cvt_tf32(fmaxf(f, 0.f));
                }
                STTM_X32(tmem + woff + T_A2 + c0, r);
            }
            TC_WAIT_ST();
        }
        TC_FENCE_BEFORE();
        __syncthreads();

        if (wid == 0) {
            TC_FENCE_AFTER();
            if (elect_one()) {
                uint64_t bd = make_desc(sb + SM_W2);
                #pragma unroll
                for (int s = 0; s < 16; s++) {
                    uint64_t off = (uint64_t)((s >> 2) * 512 + (s & 3) * 2);
                    mma_tf32_ts(tmem + T_D2, tmem + T_A2 + s * 8, bd + off, IDESC2, s > 0);
                }
                TC_COMMIT(sb + SM_MBAR);
            }
        }
        MBAR_WAIT(sb + SM_MBAR, ph); ph ^= 1;
        TC_FENCE_AFTER();

        {
            const float* b2s = (const float*)(smem + SM_B2);
            int node = base + (wid & 3) * 32 + lid;
            int c0 = wg * 32;
            uint32_t r[32];
            LDTM_X32(r, tmem + woff + T_D2 + c0);
            TC_WAIT_LD();
            if (node < N_NODES) {
                float* op = buf + (size_t)node * DIM + c0;
                #pragma unroll
                for (int g = 0; g < 8; g++) {
                    float4 v;
                    v.x = __uint_as_float(r[4 * g + 0]) + b2s[c0 + 4 * g + 0];
                    v.y = __uint_as_float(r[4 * g + 1]) + b2s[c0 + 4 * g + 1];
                    v.z = __uint_as_float(r[4 * g + 2]) + b2s[c0 + 4 * g + 2];
                    v.w = __uint_as_float(r[4 * g + 3]) + b2s[c0 + 4 * g + 3];
                    *(float4*)(op + 4 * g) = v;
                }
            }
        }
        TC_FENCE_BEFORE();
    }

    __syncthreads();
    if (wid == 0) {
        if (elect_one()) MBAR_INVAL(sb + SM_MBAR);
        TC_DEALLOC(tmem, T_COLS);
    }
#endif
}

// ---------------------------------------------------------------------------
// Launch
// ---------------------------------------------------------------------------
extern "C" void kernel_launch(void* const* d_in, const int* in_sizes, int n_in,
                              void* d_out, int out_size) {
    const float* x  = (const float*)d_in[0];
    const void*  ei = d_in[1];
    const float* W1 = (const float*)d_in[2];
    const float* b1 = (const float*)d_in[3];
    const float* W2 = (const float*)d_in[4];
    const float* b2 = (const float*)d_in[5];
    float* out = (float*)d_out;

    cudaFuncSetAttribute(mlp_tc_kernel, cudaFuncAttributeMaxDynamicSharedMemorySize,
                         SM_TOTAL);

    detect_kernel<<<1, 1>>>((const int*)ei);
    prep_w_kernel<<<(DIM * HID + 255) / 256, 256>>>(W1, W2);

    // CSR build
    zero_cnt_kernel<<<(N_NODES + 255) / 256, 256>>>();
    count_kernel<<<(N_EDGES + 255) / 256, 256>>>(ei);
    scanA_kernel<<<SCAN_BLOCKS, 1024>>>();
    scanB_kernel<<<1, 128>>>();
    scanC_kernel<<<SCAN_BLOCKS, 1024>>>();
    fill_kernel<<<(N_EDGES + 255) / 256, 256>>>(ei);

    // aggregate (self + neighbors), no float atomics
    gather_kernel<<<(N_NODES * 32 + 255) / 256, 256>>>(x, out);

    // MLP in place
    mlp_tc_kernel<<<MLP_GRID, 256, SM_TOTAL>>>(out, b1, b2);
}

// round 10
// speedup vs baseline: 1.8634x; 1.0006x over previous
#include <cuda_runtime.h>
#include <cstdint>

#define N_NODES 100000
#define N_EDGES 1600000
#define DIM 64
#define HID 128
#define TILE_M 128
#define NT 782
#define TILES_PER_CTA 3
#define MLP_GRID 261
#define SCAN_BLOCKS 98   // ceil(100000/1024)

#if defined(__CUDA_ARCH_FEAT_SM103_ALL) || defined(__CUDA_ARCH_FEAT_SM100_ALL) || \
    defined(__CUDA_ARCH_FEAT_SM101_ALL)
#define HAS_TCGEN05 1
#else
#define HAS_TCGEN05 0
#endif

__device__ int g_idx_is64;
__device__ uint32_t g_w1t[DIM * HID];
__device__ uint32_t g_w2t[HID * DIM];
__device__ int g_off[N_NODES];     // counts -> exclusive prefix -> (after fill) inclusive end
__device__ int g_csr[N_EDGES];     // src ids grouped by dst
__device__ int g_blk[128];         // block sums for the scan

// ---------------------------------------------------------------------------
// helpers
// ---------------------------------------------------------------------------
__device__ __forceinline__ uint32_t smem_u32(const void* p) {
    uint32_t a;
    asm("{ .reg .u64 t; cvta.to.shared.u64 t, %1; cvt.u32.u64 %0, t; }" : "=r"(a) : "l"(p));
    return a;
}
__device__ __forceinline__ uint32_t elect_one() {
    uint32_t p;
    asm volatile("{ .reg .pred p; elect.sync _|p, 0xFFFFFFFF; selp.b32 %0, 1, 0, p; }" : "=r"(p));
    return p;
}
__device__ __forceinline__ uint32_t sw128(uint32_t b) { return b ^ ((b >> 3) & 0x70); }
__device__ __forceinline__ uint32_t cvt_tf32(float f) {
    uint32_t r;
    asm("cvt.rna.tf32.f32 %0, %1;" : "=r"(r) : "f"(f));
    return r;
}
__device__ __forceinline__ uint64_t make_desc(uint32_t addr) {
    return (uint64_t(2) << 61) | (uint64_t(1) << 46) | (uint64_t(64) << 32) |
           (uint64_t(1) << 16) | ((uint64_t)(addr >> 4) & 0x3FFF);
}

#define MBAR_INIT(a, c) asm volatile("mbarrier.init.shared.b64 [%0], %1;" :: "r"(a), "r"(c) : "memory")
#define MBAR_INVAL(a)   asm volatile("mbarrier.inval.shared.b64 [%0];" :: "r"(a) : "memory")
#define MBAR_WAIT(a, ph) do {                                                     \
    uint32_t _m = (a), _p = (ph), _d;                                             \
    asm volatile("{ .reg .pred p; mbarrier.try_wait.parity.acquire.cta.shared::cta.b64 p, [%1], %2; selp.b32 %0,1,0,p; }" \
                 : "=r"(_d) : "r"(_m), "r"(_p) : "memory");                       \
    if (!_d) {                                                                    \
        asm volatile("{ .reg .pred P1; WL%=: mbarrier.try_wait.parity.acquire.cta.shared::cta.b64 P1, [%0], %1, 0x989680;" \
                     " @P1 bra.uni WD%=; bra.uni WL%=; WD%=: }"                   \
                     :: "r"(_m), "r"(_p) : "memory");                             \
    } } while (0)

#if HAS_TCGEN05
#define TC_ALLOC(sa, n)   asm volatile("tcgen05.alloc.cta_group::1.sync.aligned.shared::cta.b32 [%0], %1;" :: "r"(sa), "r"(n) : "memory")
#define TC_DEALLOC(t, n)  asm volatile("tcgen05.dealloc.cta_group::1.sync.aligned.b32 %0, %1;" :: "r"(t), "r"(n))
#define TC_RELINQ()       asm volatile("tcgen05.relinquish_alloc_permit.cta_group::1.sync.aligned;")
#define TC_COMMIT(mb)     asm volatile("tcgen05.commit.cta_group::1.mbarrier::arrive::one.shared::cluster.b64 [%0];" :: "r"(mb) : "memory")
#define TC_WAIT_LD()      asm volatile("tcgen05.wait::ld.sync.aligned;" ::: "memory")
#define TC_WAIT_ST()      asm volatile("tcgen05.wait::st.sync.aligned;" ::: "memory")
#define TC_FENCE_BEFORE() asm volatile("tcgen05.fence::before_thread_sync;" ::: "memory")
#define TC_FENCE_AFTER()  asm volatile("tcgen05.fence::after_thread_sync;" ::: "memory")
#define FENCE_ASYNC()     asm volatile("fence.proxy.async.shared::cta;" ::: "memory")

#define LDTM_X32(r, a)                                                              \
    asm volatile("tcgen05.ld.sync.aligned.32x32b.x32.b32 "                          \
        "{%0,%1,%2,%3,%4,%5,%6,%7,%8,%9,%10,%11,%12,%13,%14,%15,"                   \
        "%16,%17,%18,%19,%20,%21,%22,%23,%24,%25,%26,%27,%28,%29,%30,%31}, [%32];"  \
        : "=r"((r)[0]),"=r"((r)[1]),"=r"((r)[2]),"=r"((r)[3]),"=r"((r)[4]),"=r"((r)[5]),"=r"((r)[6]),"=r"((r)[7]), \
          "=r"((r)[8]),"=r"((r)[9]),"=r"((r)[10]),"=r"((r)[11]),"=r"((r)[12]),"=r"((r)[13]),"=r"((r)[14]),"=r"((r)[15]), \
          "=r"((r)[16]),"=r"((r)[17]),"=r"((r)[18]),"=r"((r)[19]),"=r"((r)[20]),"=r"((r)[21]),"=r"((r)[22]),"=r"((r)[23]), \
          "=r"((r)[24]),"=r"((r)[25]),"=r"((r)[26]),"=r"((r)[27]),"=r"((r)[28]),"=r"((r)[29]),"=r"((r)[30]),"=r"((r)[31]) \
        : "r"(a))

#define STTM_X32(a, r)                                                              \
    asm volatile("tcgen05.st.sync.aligned.32x32b.x32.b32 [%0], "                    \
        "{%1,%2,%3,%4,%5,%6,%7,%8,%9,%10,%11,%12,%13,%14,%15,%16,"                  \
        "%17,%18,%19,%20,%21,%22,%23,%24,%25,%26,%27,%28,%29,%30,%31,%32};"         \
        :: "r"(a),                                                                  \
           "r"((r)[0]),"r"((r)[1]),"r"((r)[2]),"r"((r)[3]),"r"((r)[4]),"r"((r)[5]),"r"((r)[6]),"r"((r)[7]), \
           "r"((r)[8]),"r"((r)[9]),"r"((r)[10]),"r"((r)[11]),"r"((r)[12]),"r"((r)[13]),"r"((r)[14]),"r"((r)[15]), \
           "r"((r)[16]),"r"((r)[17]),"r"((r)[18]),"r"((r)[19]),"r"((r)[20]),"r"((r)[21]),"r"((r)[22]),"r"((r)[23]), \
           "r"((r)[24]),"r"((r)[25]),"r"((r)[26]),"r"((r)[27]),"r"((r)[28]),"r"((r)[29]),"r"((r)[30]),"r"((r)[31]) \
        : "memory")

__device__ __forceinline__ void mma_tf32_ss(uint32_t d, uint64_t a, uint64_t b,
                                            uint32_t idesc, bool acc) {
    uint32_t e = acc ? 1u : 0u;
    asm volatile("{ .reg .pred p; setp.ne.u32 p, %4, 0;"
                 " tcgen05.mma.cta_group::1.kind::tf32 [%0], %1, %2, %3, p; }"
                 :: "r"(d), "l"(a), "l"(b), "r"(idesc), "r"(e) : "memory");
}
__device__ __forceinline__ void mma_tf32_ts(uint32_t d, uint32_t a, uint64_t b,
                                            uint32_t idesc, bool acc) {
    uint32_t e = acc ? 1u : 0u;
    asm volatile("{ .reg .pred p; setp.ne.u32 p, %4, 0;"
                 " tcgen05.mma.cta_group::1.kind::tf32 [%0], [%1], %2, %3, p; }"
                 :: "r"(d), "r"(a), "l"(b), "r"(idesc), "r"(e) : "memory");
}
#endif

// ---------------------------------------------------------------------------
// Kernel 0: detect int32 vs int64 edge index
// ---------------------------------------------------------------------------
__global__ void detect_kernel(const int* __restrict__ ei32) {
    int any = 0;
    #pragma unroll
    for (int i = 0; i < 64; i++) any |= ei32[2 * i + 1];
    g_idx_is64 = (any == 0) ? 1 : 0;
}

// ---------------------------------------------------------------------------
// Kernel 0b: precompute swizzled tf32 weight images
// ---------------------------------------------------------------------------
__global__ void prep_w_kernel(const float* __restrict__ W1,
                              const float* __restrict__ W2) {
    int idx = blockIdx.x * blockDim.x + threadIdx.x;
    if (idx >= DIM * HID) return;
    {
        int j = idx & 127, k = idx >> 7;
        uint32_t byte = ((j >> 3) + (k >> 5) * 16) * 1024 + (j & 7) * 128 + (k & 31) * 4;
        g_w1t[sw128(byte) >> 2] = cvt_tf32(W1[k * HID + j]);
    }
    {
        int d = idx & 63, k = idx >> 6;
        uint32_t byte = ((d >> 3) + (k >> 5) * 8) * 1024 + (d & 7) * 128 + (k & 31) * 4;
        g_w2t[sw128(byte) >> 2] = cvt_tf32(W2[k * DIM + d]);
    }
}

// ---------------------------------------------------------------------------
// CSR build: zero -> count(x4) -> coalesced 3-phase scan -> fill(x4)
// ---------------------------------------------------------------------------
__global__ void zero_cnt_kernel() {
    int i = blockIdx.x * blockDim.x + threadIdx.x;
    if (i < N_NODES) g_off[i] = 0;
}

// 4 edges per thread, int4 vector load of dst -> 4-deep ILP
__global__ void count_kernel(const void* __restrict__ ei_raw) {
    int q = blockIdx.x * blockDim.x + threadIdx.x;
    if (q >= N_EDGES / 4) return;
    if (!g_idx_is64) {
        const int4* dp = (const int4*)((const int*)ei_raw + N_EDGES);
        int4 d = __ldg(dp + q);
        if ((unsigned)d.x < N_NODES) atomicAdd(&g_off[d.x], 1);
        if ((unsigned)d.y < N_NODES) atomicAdd(&g_off[d.y], 1);
        if ((unsigned)d.z < N_NODES) atomicAdd(&g_off[d.z], 1);
        if ((unsigned)d.w < N_NODES) atomicAdd(&g_off[d.w], 1);
    } else {
        const longlong2* dp = (const longlong2*)((const long long*)ei_raw + N_EDGES);
        longlong2 d0 = __ldg(dp + 2 * q);
        longlong2 d1 = __ldg(dp + 2 * q + 1);
        if ((unsigned long long)d0.x < N_NODES) atomicAdd(&g_off[(int)d0.x], 1);
        if ((unsigned long long)d0.y < N_NODES) atomicAdd(&g_off[(int)d0.y], 1);
        if ((unsigned long long)d1.x < N_NODES) atomicAdd(&g_off[(int)d1.x], 1);
        if ((unsigned long long)d1.y < N_NODES) atomicAdd(&g_off[(int)d1.y], 1);
    }
}

// scanA: per-1024-block sums (coalesced)
__global__ __launch_bounds__(1024) void scanA_kernel() {
    int i = blockIdx.x * 1024 + threadIdx.x;
    int v = (i < N_NODES) ? g_off[i] : 0;
    #pragma unroll
    for (int o = 16; o > 0; o >>= 1) v += __shfl_down_sync(0xffffffffu, v, o);
    __shared__ int ws[32];
    if ((threadIdx.x & 31) == 0) ws[threadIdx.x >> 5] = v;
    __syncthreads();
    if (threadIdx.x < 32) {
        int s = ws[threadIdx.x];
        #pragma unroll
        for (int o = 16; o > 0; o >>= 1) s += __shfl_down_sync(0xffffffffu, s, o);
        if (threadIdx.x == 0) g_blk[blockIdx.x] = s;
    }
}

// scanB: exclusive scan of the 98 block sums
__global__ __launch_bounds__(128) void scanB_kernel() {
    __shared__ int ts[128];
    int t = threadIdx.x;
    int v = (t < SCAN_BLOCKS) ? g_blk[t] : 0;
    ts[t] = v;
    __syncthreads();
    #pragma unroll
    for (int o = 1; o < 128; o <<= 1) {
        int u = (t >= o) ? ts[t - o] : 0;
        __syncthreads();
        ts[t] += u;
        __syncthreads();
    }
    if (t < SCAN_BLOCKS) g_blk[t] = ts[t] - v;   // exclusive
}

// scanC: per-element exclusive prefix within block + block offset (coalesced)
__global__ __launch_bounds__(1024) void scanC_kernel() {
    int t = threadIdx.x;
    int lane = t & 31, w = t >> 5;
    int i = blockIdx.x * 1024 + t;
    int v = (i < N_NODES) ? g_off[i] : 0;

    int s = v;
    #pragma unroll
    for (int o = 1; o < 32; o <<= 1) {
        int u = __shfl_up_sync(0xffffffffu, s, o);
        if (lane >= o) s += u;
    }
    __shared__ int ws[32];
    if (lane == 31) ws[w] = s;
    __syncthreads();
    if (w == 0) {
        int x2 = ws[lane];
        #pragma unroll
        for (int o = 1; o < 32; o <<= 1) {
            int u = __shfl_up_sync(0xffffffffu, x2, o);
            if (lane >= o) x2 += u;
        }
        ws[lane] = x2;
    }
    __syncthreads();
    int warp_excl = (w == 0) ? 0 : ws[w - 1];
    int excl = (s - v) + warp_excl + g_blk[blockIdx.x];
    if (i < N_NODES) g_off[i] = excl;
}

// 4 edges per thread, int4 loads of src and dst
__global__ void fill_kernel(const void* __restrict__ ei_raw) {
    int q = blockIdx.x * blockDim.x + threadIdx.x;
    if (q >= N_EDGES / 4) return;
    int s0, s1, s2, s3, d0, d1, d2, d3;
    if (!g_idx_is64) {
        const int4* sp = (const int4*)((const int*)ei_raw);
        const int4* dp = (const int4*)((const int*)ei_raw + N_EDGES);
        int4 s = __ldg(sp + q);
        int4 d = __ldg(dp + q);
        s0 = s.x; s1 = s.y; s2 = s.z; s3 = s.w;
        d0 = d.x; d1 = d.y; d2 = d.z; d3 = d.w;
    } else {
        const longlong2* sp = (const longlong2*)((const long long*)ei_raw);
        const longlong2* dp = (const longlong2*)((const long long*)ei_raw + N_EDGES);
        longlong2 sa = __ldg(sp + 2 * q), sb = __ldg(sp + 2 * q + 1);
        longlong2 da = __ldg(dp + 2 * q), db = __ldg(dp + 2 * q + 1);
        s0 = (int)sa.x; s1 = (int)sa.y; s2 = (int)sb.x; s3 = (int)sb.y;
        d0 = (int)da.x; d1 = (int)da.y; d2 = (int)db.x; d3 = (int)db.y;
    }
    if ((unsigned)d0 < N_NODES && (unsigned)s0 < N_NODES)
        g_csr[atomicAdd(&g_off[d0], 1)] = s0;
    if ((unsigned)d1 < N_NODES && (unsigned)s1 < N_NODES)
        g_csr[atomicAdd(&g_off[d1], 1)] = s1;
    if ((unsigned)d2 < N_NODES && (unsigned)s2 < N_NODES)
        g_csr[atomicAdd(&g_off[d2], 1)] = s2;
    if ((unsigned)d3 < N_NODES && (unsigned)s3 < N_NODES)
        g_csr[atomicAdd(&g_off[d3], 1)] = s3;
}

// ---------------------------------------------------------------------------
// Gather-aggregate: warp per node, lane = float2 slice; staged indices,
// groups of 8 independent LDG.64 into 4 accumulators.
// ---------------------------------------------------------------------------
__global__ __launch_bounds__(256) void gather_kernel(const float* __restrict__ x,
                                                     float* __restrict__ out) {
    __shared__ int stage[8][132];
    int wl = threadIdx.x >> 5;
    int w  = (blockIdx.x * blockDim.x + threadIdx.x) >> 5;
    if (w >= N_NODES) return;
    int lane = threadIdx.x & 31;

    int end   = g_off[w];
    int start = (w == 0) ? 0 : g_off[w - 1];

    const float2* xp = (const float2*)x;
    float2 a0 = __ldg(xp + (size_t)w * 32 + lane);   // self term
    float2 a1 = make_float2(0.f, 0.f);
    float2 a2 = make_float2(0.f, 0.f);
    float2 a3 = make_float2(0.f, 0.f);

    for (int b = start; b < end; b += 128) {
        int m = min(128, end - b);
        for (int i = lane; i < m; i += 32) stage[wl][i] = __ldg(&g_csr[b + i]);
        __syncwarp();

        int i = 0;
        for (; i + 8 <= m; i += 8) {
            int n0 = stage[wl][i + 0], n1 = stage[wl][i + 1];
            int n2 = stage[wl][i + 2], n3 = stage[wl][i + 3];
            int n4 = stage[wl][i + 4], n5 = stage[wl][i + 5];
            int n6 = stage[wl][i + 6], n7 = stage[wl][i + 7];
            float2 v0 = __ldg(xp + (size_t)n0 * 32 + lane);
            float2 v1 = __ldg(xp + (size_t)n1 * 32 + lane);
            float2 v2 = __ldg(xp + (size_t)n2 * 32 + lane);
            float2 v3 = __ldg(xp + (size_t)n3 * 32 + lane);
            float2 v4 = __ldg(xp + (size_t)n4 * 32 + lane);
            float2 v5 = __ldg(xp + (size_t)n5 * 32 + lane);
            float2 v6 = __ldg(xp + (size_t)n6 * 32 + lane);
            float2 v7 = __ldg(xp + (size_t)n7 * 32 + lane);
            a0.x += v0.x; a0.y += v0.y;  a1.x += v1.x; a1.y += v1.y;
            a2.x += v2.x; a2.y += v2.y;  a3.x += v3.x; a3.y += v3.y;
            a0.x += v4.x; a0.y += v4.y;  a1.x += v5.x; a1.y += v5.y;
            a2.x += v6.x; a2.y += v6.y;  a3.x += v7.x; a3.y += v7.y;
        }
        for (; i < m; i++) {
            int nb = stage[wl][i];
            float2 v = __ldg(xp + (size_t)nb * 32 + lane);
            a0.x += v.x; a0.y += v.y;
        }
        __syncwarp();
    }

    a0.x += a1.x + a2.x + a3.x;
    a0.y += a1.y + a2.y + a3.y;
    *((float2*)(out + (size_t)w * DIM) + lane) = a0;
}

// ---------------------------------------------------------------------------
// MLP via tcgen05 (buf already holds self+neighbors)
// ---------------------------------------------------------------------------
#define SM_TMEM  0
#define SM_MBAR  8
#define SM_X     1024
#define SM_W1    (SM_X + 32768)
#define SM_W2    (SM_W1 + 32768)
#define SM_B1    (SM_W2 + 32768)
#define SM_B2    (SM_B1 + 512)
#define SM_TOTAL (SM_B2 + 512)

#define T_D1   0
#define T_A2   128
#define T_D2   0
#define T_COLS 256

#define IDESC1 ((1u << 4) | (2u << 7) | (2u << 10) | ((HID / 8) << 17) | ((TILE_M / 16) << 24))
#define IDESC2 ((1u << 4) | (2u << 7) | (2u << 10) | ((DIM / 8) << 17) | ((TILE_M / 16) << 24))

__global__ __launch_bounds__(256, 2)
void mlp_tc_kernel(float* __restrict__ buf,
                   const float* __restrict__ b1, const float* __restrict__ b2) {
#if HAS_TCGEN05
    extern __shared__ char smem[];
    uint32_t sb = smem_u32(smem);
    int tid = threadIdx.x;
    int wid = tid >> 5;
    int lid = tid & 31;
    int wg  = wid >> 2;
    uint32_t woff = (uint32_t)(wid & 3) << 21;

    if (wid == 0) {
        TC_ALLOC(sb + SM_TMEM, T_COLS);
        TC_RELINQ();
        if (elect_one()) MBAR_INIT(sb + SM_MBAR, 1);
    }
    __syncthreads();
    uint32_t tmem;
    asm volatile("ld.shared.b32 %0, [%1];" : "=r"(tmem) : "r"(sb + SM_TMEM));

    {
        const uint4* s1 = (const uint4*)g_w1t;
        const uint4* s2 = (const uint4*)g_w2t;
        uint4* d1 = (uint4*)(smem + SM_W1);
        uint4* d2 = (uint4*)(smem + SM_W2);
        for (int i = tid; i < DIM * HID / 4; i += 256) {
            d1[i] = __ldg(s1 + i);
            d2[i] = __ldg(s2 + i);
        }
    }
    if (tid < HID) ((float*)(smem + SM_B1))[tid] = b1[tid];
    if (tid < DIM) ((float*)(smem + SM_B2))[tid] = b2[tid];

    int ph = 0;
    #pragma unroll 1
    for (int t = 0; t < TILES_PER_CTA; t++) {
        int tile = blockIdx.x * TILES_PER_CTA + t;
        if (tile >= NT) break;
        int base = tile * TILE_M;

        __syncthreads();

        for (int i = tid; i < TILE_M * (DIM / 4); i += 256) {
            int row = i >> 4;
            int c4  = i & 15;
            int node = base + row;
            float4 s = make_float4(0.f, 0.f, 0.f, 0.f);
            if (node < N_NODES)
                s = __ldg(((const float4*)(buf + (size_t)node * DIM)) + c4);
            uint32_t byte = ((row >> 3) + (c4 >> 3) * 16) * 1024 + (row & 7) * 128 + (c4 & 7) * 16;
            *(uint4*)(smem + SM_X + sw128(byte)) =
                make_uint4(cvt_tf32(s.x), cvt_tf32(s.y), cvt_tf32(s.z), cvt_tf32(s.w));
        }
        FENCE_ASYNC();
        __syncthreads();

        if (wid == 0) {
            TC_FENCE_AFTER();
            if (elect_one()) {
                uint64_t ad = make_desc(sb + SM_X);
                uint64_t bd = make_desc(sb + SM_W1);
                #pragma unroll
                for (int s = 0; s < 8; s++) {
                    uint64_t off = (uint64_t)((s >> 2) * 1024 + (s & 3) * 2);
                    mma_tf32_ss(tmem + T_D1, ad + off, bd + off, IDESC1, s > 0);
                }
                TC_COMMIT(sb + SM_MBAR);
            }
        }
        MBAR_WAIT(sb + SM_MBAR, ph); ph ^= 1;
        TC_FENCE_AFTER();

        {
            const float* b1s = (const float*)(smem + SM_B1);
            #pragma unroll
            for (int blk = 0; blk < 2; blk++) {
                int c0 = wg * 64 + blk * 32;
                uint32_t r[32];
                LDTM_X32(r, tmem + woff + T_D1 + c0);
                TC_WAIT_LD();
                #pragma unroll
                for (int i = 0; i < 32; i++) {
                    float f = __uint_as_float(r[i]) + b1s[c0 + i];
                    r[i] = cvt_tf32(fmaxf(f, 0.f));
                }
                STTM_X32(tmem + woff + T_A2 + c0, r);
            }
            TC_WAIT_ST();
        }
        TC_FENCE_BEFORE();
        __syncthreads();

        if (wid == 0) {
            TC_FENCE_AFTER();
            if (elect_one()) {
                uint64_t bd = make_desc(sb + SM_W2);
                #pragma unroll
                for (int s = 0; s < 16; s++) {
                    uint64_t off = (uint64_t)((s >> 2) * 512 + (s & 3) * 2);
                    mma_tf32_ts(tmem + T_D2, tmem + T_A2 + s * 8, bd + off, IDESC2, s > 0);
                }
                TC_COMMIT(sb + SM_MBAR);
            }
        }
        MBAR_WAIT(sb + SM_MBAR, ph); ph ^= 1;
        TC_FENCE_AFTER();

        {
            const float* b2s = (const float*)(smem + SM_B2);
            int node = base + (wid & 3) * 32 + lid;
            int c0 = wg * 32;
            uint32_t r[32];
            LDTM_X32(r, tmem + woff + T_D2 + c0);
            TC_WAIT_LD();
            if (node < N_NODES) {
                float* op = buf + (size_t)node * DIM + c0;
                #pragma unroll
                for (int g = 0; g < 8; g++) {
                    float4 v;
                    v.x = __uint_as_float(r[4 * g + 0]) + b2s[c0 + 4 * g + 0];
                    v.y = __uint_as_float(r[4 * g + 1]) + b2s[c0 + 4 * g + 1];
                    v.z = __uint_as_float(r[4 * g + 2]) + b2s[c0 + 4 * g + 2];
                    v.w = __uint_as_float(r[4 * g + 3]) + b2s[c0 + 4 * g + 3];
                    *(float4*)(op + 4 * g) = v;
                }
            }
        }
        TC_FENCE_BEFORE();
    }

    __syncthreads();
    if (wid == 0) {
        if (elect_one()) MBAR_INVAL(sb + SM_MBAR);
        TC_DEALLOC(tmem, T_COLS);
    }
#endif
}

// ---------------------------------------------------------------------------
// Launch
// ---------------------------------------------------------------------------
extern "C" void kernel_launch(void* const* d_in, const int* in_sizes, int n_in,
                              void* d_out, int out_size) {
    const float* x  = (const float*)d_in[0];
    const void*  ei = d_in[1];
    const float* W1 = (const float*)d_in[2];
    const float* b1 = (const float*)d_in[3];
    const float* W2 = (const float*)d_in[4];
    const float* b2 = (const float*)d_in[5];
    float* out = (float*)d_out;

    cudaFuncSetAttribute(mlp_tc_kernel, cudaFuncAttributeMaxDynamicSharedMemorySize,
                         SM_TOTAL);

    detect_kernel<<<1, 1>>>((const int*)ei);
    prep_w_kernel<<<(DIM * HID + 255) / 256, 256>>>(W1, W2);

    // CSR build
    zero_cnt_kernel<<<(N_NODES + 255) / 256, 256>>>();
    count_kernel<<<(N_EDGES / 4 + 255) / 256, 256>>>(ei);
    scanA_kernel<<<SCAN_BLOCKS, 1024>>>();
    scanB_kernel<<<1, 128>>>();
    scanC_kernel<<<SCAN_BLOCKS, 1024>>>();
    fill_kernel<<<(N_EDGES / 4 + 255) / 256, 256>>>(ei);

    // aggregate (self + neighbors), no float atomics
    gather_kernel<<<(N_NODES * 32 + 255) / 256, 256>>>(x, out);

    // MLP in place
    mlp_tc_kernel<<<MLP_GRID, 256, SM_TOTAL>>>(out, b1, b2);
}